// round 6
// baseline (speedup 1.0000x reference)
#include <cuda_runtime.h>
#include <math.h>

#define BB  16
#define CC  64
#define HH  128
#define WW  128
#define HW  (HH*WW)
#define BC  (BB*CC)
#define GRP 4             // channel groups
#define CPG (CC/GRP)      // channels per group = 16

// Per-(b,c) x-space threshold T = logit(sigmoid(max x) - 0.01), from k1.
__device__ float g_T[BC];
// Partial (max, argmax) per branch(3) x group(4) x (b,pixel): .x=val, .y=idx bits
__device__ float2 g_part[3][GRP][BB * HW];

__device__ __forceinline__ float sigmoidf_(float v) {
    return 1.0f / (1.0f + expf(-v));
}

// ---------------------------------------------------------------------------
// K1: per-(b,c) plane. max(x) -> ps, threshold T; masked sums -> bbox row.
// ---------------------------------------------------------------------------
__global__ __launch_bounds__(256) void k1_stats(
    const float* __restrict__ x,
    const float* __restrict__ w_bbx,
    const float* __restrict__ w_width,
    const float* __restrict__ w_width_sh,
    const float* __restrict__ w_height,
    const float* __restrict__ w_height_sh,
    float* __restrict__ out)
{
    const int bc = blockIdx.x;
    const int b  = bc / CC;
    const int c  = bc % CC;
    const float* __restrict__ xp = x + (size_t)bc * HW;
    const int t = threadIdx.x;

    float mx = -INFINITY;
    #pragma unroll
    for (int j = 0; j < 16; ++j) {
        float4 v = *(const float4*)(xp + 1024 * j + 4 * t);
        mx = fmaxf(fmaxf(fmaxf(mx, v.x), fmaxf(v.y, v.z)), v.w);
    }
    __shared__ float red[8];
    #pragma unroll
    for (int o = 16; o; o >>= 1) mx = fmaxf(mx, __shfl_xor_sync(0xffffffffu, mx, o));
    if ((t & 31) == 0) red[t >> 5] = mx;
    __syncthreads();
    __shared__ float sT, sps;
    if (t == 0) {
        float v = red[0];
        #pragma unroll
        for (int k = 1; k < 8; ++k) v = fmaxf(v, red[k]);
        float ps = sigmoidf_(v);
        float M  = ps - 0.01f;
        float T;
        if (M > 0.0f) {
            double dM = (double)M;
            T = (float)log(dM / (1.0 - dM));
        } else {
            T = -INFINITY;
        }
        sT = T; sps = ps;
        g_T[bc] = T;
    }
    __syncthreads();
    const float T = sT;

    float cw[11], ch[11];
    #pragma unroll
    for (int k = 0; k < 11; ++k) { cw[k] = w_width[c*11+k]; ch[k] = w_height[c*11+k]; }
    const float s0 = w_bbx[c] * 128.0f;
    const float sW = s0 * w_width_sh[c];
    const float sH = s0 * w_height_sh[c];

    float S = 0.f, Sc = 0.f, Sr = 0.f, Sw = 0.f, Sh = 0.f;
    #pragma unroll
    for (int j = 0; j < 16; ++j) {
        const int i0 = 1024 * j + 4 * t;
        float4 v4 = *(const float4*)(xp + i0);
        float vv[4] = {v4.x, v4.y, v4.z, v4.w};
        if (vv[0] > T || vv[1] > T || vv[2] > T || vv[3] > T) {
            #pragma unroll
            for (int u = 0; u < 4; ++u) {
                float v = vv[u];
                if (v > T) {
                    int i = i0 + u;
                    int row = i >> 7, col = i & 127;
                    S  += v;
                    Sc += (float)col * v;
                    Sr += (float)row * v;
                    float wvv = 0.f;
                    #pragma unroll
                    for (int k = 0; k < 11; ++k) {
                        int cc2 = col - 5 + k;
                        if (cc2 >= 0 && cc2 < WW) wvv = fmaf(xp[(row << 7) + cc2], cw[k], wvv);
                    }
                    float hvv = 0.f;
                    #pragma unroll
                    for (int k = 0; k < 11; ++k) {
                        int rr = row - 5 + k;
                        if (rr >= 0 && rr < HH) hvv = fmaf(xp[(rr << 7) + col], ch[k], hvv);
                    }
                    Sw += wvv * sW * v;
                    Sh += hvv * sH * v;
                }
            }
        }
    }
    __shared__ float racc[5][8];
    #pragma unroll
    for (int o = 16; o; o >>= 1) {
        S  += __shfl_xor_sync(0xffffffffu, S,  o);
        Sc += __shfl_xor_sync(0xffffffffu, Sc, o);
        Sr += __shfl_xor_sync(0xffffffffu, Sr, o);
        Sw += __shfl_xor_sync(0xffffffffu, Sw, o);
        Sh += __shfl_xor_sync(0xffffffffu, Sh, o);
    }
    if ((t & 31) == 0) {
        int w5 = t >> 5;
        racc[0][w5] = S; racc[1][w5] = Sc; racc[2][w5] = Sr; racc[3][w5] = Sw; racc[4][w5] = Sh;
    }
    __syncthreads();
    if (t == 0) {
        float a0=0,a1=0,a2=0,a3=0,a4=0;
        #pragma unroll
        for (int k = 0; k < 8; ++k) { a0+=racc[0][k]; a1+=racc[1][k]; a2+=racc[2][k]; a3+=racc[3][k]; a4+=racc[4][k]; }
        float ws = a3 / a0, hs = a4 / a0;
        float x1 = a1 / a0 - ws * 0.5f;
        float y1 = a2 / a0 - hs * 0.5f;
        float* bb = out + (size_t)BB * 3 * CC * HW + (size_t)bc * 6;
        bb[0] = (float)b; bb[1] = x1; bb[2] = y1;
        bb[3] = x1 + ws;  bb[4] = y1 + hs; bb[5] = sps;
    }
}

// ---------------------------------------------------------------------------
// K2a: partial channel sweep (16 channels per block). Tracks (max, argmax)
// per pixel per branch in registers; writes partials to g_part.
// 256 threads: r = t>>5 (8 rows), c4 = (t&31)<<2 (4 cols).
// ---------------------------------------------------------------------------
#define RG 8
#define TR 18
#define TP 144
#define NFILL 9

__global__ __launch_bounds__(256) void k2a_partial(
    const float* __restrict__ x,
    const float* __restrict__ w_bbx,
    const float* __restrict__ w_width,
    const float* __restrict__ w_width_sh,
    const float* __restrict__ w_height,
    const float* __restrict__ w_height_sh)
{
    __shared__ float tile[2][TR * TP];
    __shared__ float scw[CPG * 11], sch[CPG * 11];
    __shared__ float ssW[CPG], ssH[CPG], sTv[CPG];

    const int t    = threadIdx.x;
    const int b    = blockIdx.z;
    const int cg   = blockIdx.y;          // 0..3
    const int rg   = blockIdx.x;          // 0..15
    const int cbase = cg * CPG;
    const int row0 = rg * RG;
    const int r    = t >> 5;
    const int c4   = (t & 31) << 2;
    const int grow = row0 + r;

    for (int i = t; i < TR * TP; i += 256) {
        int col = i % TP;
        if (col < 8 || col >= 136) { tile[0][i] = 0.f; tile[1][i] = 0.f; }
    }
    if (t < CPG * 11) {
        scw[t] = w_width[cbase * 11 + t];
        sch[t] = w_height[cbase * 11 + t];
    }
    if (t >= 224 && t < 224 + CPG) {
        int lc = t - 224;
        float s0 = w_bbx[cbase + lc] * 128.0f;
        ssW[lc] = s0 * w_width_sh[cbase + lc];
        ssH[lc] = s0 * w_height_sh[cbase + lc];
        sTv[lc] = g_T[b * CC + cbase + lc];
    }

    int   fjr[NFILL], fcol[NFILL];
    bool  fok[NFILL];
    #pragma unroll
    for (int j = 0; j < NFILL; ++j) {
        int idx = t + j * 256;
        fjr[j]  = idx >> 7;
        fcol[j] = idx & 127;
        int gr  = row0 - 5 + fjr[j];
        fok[j]  = (gr >= 0 && gr < HH);
    }
    const int gbase0 = (row0 - 5) << 7;

    float regs[NFILL];
    const float* xp0 = x + ((size_t)(b * CC + cbase)) * HW;

    {
        const float* xp = xp0;
        #pragma unroll
        for (int j = 0; j < NFILL; ++j)
            regs[j] = fok[j] ? __ldg(xp + gbase0 + (fjr[j] << 7) + fcol[j]) : 0.f;
        #pragma unroll
        for (int j = 0; j < NFILL; ++j)
            tile[0][fjr[j] * TP + 8 + fcol[j]] = regs[j];
    }

    float mS[4], mW[4], mH[4];
    int   iS[4], iW[4], iH[4];
    #pragma unroll
    for (int j = 0; j < 4; ++j) {
        mS[j] = -INFINITY; mW[j] = -INFINITY; mH[j] = -INFINITY;
        iS[j] = cbase; iW[j] = cbase; iH[j] = cbase;
    }

    for (int lc = 0; lc < CPG; ++lc) {
        const int cur = lc & 1;
        if (lc + 1 < CPG) {
            const float* xp = xp0 + (size_t)(lc + 1) * HW;
            #pragma unroll
            for (int j = 0; j < NFILL; ++j)
                regs[j] = fok[j] ? __ldg(xp + gbase0 + (fjr[j] << 7) + fcol[j]) : 0.f;
        }
        __syncthreads();

        const float* tl = tile[cur];
        float in[20];
        {
            const float* hrow = &tl[(r + 5) * TP + c4];
            #pragma unroll
            for (int m = 0; m < 5; ++m) {
                float4 v = *(const float4*)(hrow + 4 * m);
                in[4*m+0] = v.x; in[4*m+1] = v.y; in[4*m+2] = v.z; in[4*m+3] = v.w;
            }
        }
        float hv[4] = {0.f, 0.f, 0.f, 0.f};
        #pragma unroll
        for (int k = 0; k < 11; ++k) {
            float4 v = *(const float4*)(&tl[(r + k) * TP + 8 + c4]);
            float ck = sch[lc * 11 + k];
            hv[0] = fmaf(v.x, ck, hv[0]);
            hv[1] = fmaf(v.y, ck, hv[1]);
            hv[2] = fmaf(v.z, ck, hv[2]);
            hv[3] = fmaf(v.w, ck, hv[3]);
        }
        float wv[4] = {0.f, 0.f, 0.f, 0.f};
        #pragma unroll
        for (int k = 0; k < 11; ++k) {
            float ck = scw[lc * 11 + k];
            wv[0] = fmaf(in[3 + k], ck, wv[0]);
            wv[1] = fmaf(in[4 + k], ck, wv[1]);
            wv[2] = fmaf(in[5 + k], ck, wv[2]);
            wv[3] = fmaf(in[6 + k], ck, wv[3]);
        }
        const float sWc = ssW[lc], sHc = ssH[lc], Tc = sTv[lc];
        const int c = cbase + lc;
        #pragma unroll
        for (int j = 0; j < 4; ++j) {
            float w_ = wv[j] * sWc;
            float h_ = hv[j] * sHc;
            float xv = in[8 + j];
            float s_ = (xv > Tc) ? xv : 0.f;
            if (s_ > mS[j]) { mS[j] = s_; iS[j] = c; }
            if (w_ > mW[j]) { mW[j] = w_; iW[j] = c; }
            if (h_ > mH[j]) { mH[j] = h_; iH[j] = c; }
        }

        if (lc + 1 < CPG) {
            float* tn = tile[cur ^ 1];
            #pragma unroll
            for (int j = 0; j < NFILL; ++j)
                tn[fjr[j] * TP + 8 + fcol[j]] = regs[j];
        }
    }

    const size_t pb = (size_t)b * HW + ((size_t)grow << 7) + c4;
    {
        float4* d = (float4*)(&g_part[0][cg][pb]);
        d[0] = make_float4(mS[0], __int_as_float(iS[0]), mS[1], __int_as_float(iS[1]));
        d[1] = make_float4(mS[2], __int_as_float(iS[2]), mS[3], __int_as_float(iS[3]));
    }
    {
        float4* d = (float4*)(&g_part[1][cg][pb]);
        d[0] = make_float4(mW[0], __int_as_float(iW[0]), mW[1], __int_as_float(iW[1]));
        d[1] = make_float4(mW[2], __int_as_float(iW[2]), mW[3], __int_as_float(iW[3]));
    }
    {
        float4* d = (float4*)(&g_part[2][cg][pb]);
        d[0] = make_float4(mH[0], __int_as_float(iH[0]), mH[1], __int_as_float(iH[1]));
        d[1] = make_float4(mH[2], __int_as_float(iH[2]), mH[3], __int_as_float(iH[3]));
    }
}

// ---------------------------------------------------------------------------
// K2b: merge partials (groups ascending, strict >) and stream the dense
// masked output:  out[c] = (argmax == c) ? max : 0.
// 256 threads x 4 px; grid (16 chunks, BB).
// ---------------------------------------------------------------------------
__global__ __launch_bounds__(256) void k2b_write(float* __restrict__ out)
{
    const int t  = threadIdx.x;
    const int b  = blockIdx.y;
    const int px0 = blockIdx.x * 1024 + t * 4;
    const size_t pb = (size_t)b * HW + px0;

    float mv[3][4];
    int   mi[3][4];
    #pragma unroll
    for (int br = 0; br < 3; ++br)
        #pragma unroll
        for (int j = 0; j < 4; ++j) { mv[br][j] = -INFINITY; mi[br][j] = 0; }

    #pragma unroll
    for (int br = 0; br < 3; ++br) {
        #pragma unroll
        for (int g = 0; g < GRP; ++g) {
            const float4* s = (const float4*)(&g_part[br][g][pb]);
            float4 lo = s[0], hi = s[1];
            if (lo.x > mv[br][0]) { mv[br][0] = lo.x; mi[br][0] = __float_as_int(lo.y); }
            if (lo.z > mv[br][1]) { mv[br][1] = lo.z; mi[br][1] = __float_as_int(lo.w); }
            if (hi.x > mv[br][2]) { mv[br][2] = hi.x; mi[br][2] = __float_as_int(hi.y); }
            if (hi.z > mv[br][3]) { mv[br][3] = hi.z; mi[br][3] = __float_as_int(hi.w); }
        }
    }

    float* oS = out + (size_t)(b * 3 * CC) * HW + px0;
    float* oW = oS + (size_t)CC * HW;
    float* oH = oS + (size_t)2 * CC * HW;
    for (int c = 0; c < CC; ++c) {
        float4 vS = make_float4(mi[0][0]==c ? mv[0][0] : 0.f, mi[0][1]==c ? mv[0][1] : 0.f,
                                mi[0][2]==c ? mv[0][2] : 0.f, mi[0][3]==c ? mv[0][3] : 0.f);
        float4 vW = make_float4(mi[1][0]==c ? mv[1][0] : 0.f, mi[1][1]==c ? mv[1][1] : 0.f,
                                mi[1][2]==c ? mv[1][2] : 0.f, mi[1][3]==c ? mv[1][3] : 0.f);
        float4 vH = make_float4(mi[2][0]==c ? mv[2][0] : 0.f, mi[2][1]==c ? mv[2][1] : 0.f,
                                mi[2][2]==c ? mv[2][2] : 0.f, mi[2][3]==c ? mv[2][3] : 0.f);
        const size_t off = (size_t)c * HW;
        __stcs((float4*)(oS + off), vS);
        __stcs((float4*)(oW + off), vW);
        __stcs((float4*)(oH + off), vH);
    }
}

extern "C" void kernel_launch(void* const* d_in, const int* in_sizes, int n_in,
                              void* d_out, int out_size)
{
    const float* x           = (const float*)d_in[0];
    const float* w_bbx       = (const float*)d_in[1];
    const float* w_width     = (const float*)d_in[2];
    const float* w_width_sh  = (const float*)d_in[3];
    const float* w_height    = (const float*)d_in[4];
    const float* w_height_sh = (const float*)d_in[5];
    float* out = (float*)d_out;

    k1_stats<<<BC, 256>>>(x, w_bbx, w_width, w_width_sh, w_height, w_height_sh, out);

    dim3 g2(16, GRP, BB);
    k2a_partial<<<g2, 256>>>(x, w_bbx, w_width, w_width_sh, w_height, w_height_sh);

    dim3 g3(16, BB);
    k2b_write<<<g3, 256>>>(out);
}